// round 11
// baseline (speedup 1.0000x reference)
#include <cuda_runtime.h>
#include <cuda.h>
#include <cstdint>

// Problem dims (fixed)
#define NB   256
#define LL   2048
#define QK   512
#define HH   128

#define ROWS_PER_CTA 128
#define SPLITS       (LL / ROWS_PER_CTA)    // 16
#define NCTAS        (NB * SPLITS)          // 4096
#define THREADS      256
#define NBIG         8                      // big chunks of K=64
#define NCH32        16                     // fp32 TMA chunks of K=32

#define A32_STAGE 16384                     // 128 rows x 128B fp32 (K=32)
#define A16_STAGE 16384                     // 128 rows x 128B fp16 (K=64)
#define B16_STAGE 16384                     // 128 rows x 128B fp16 (K=64)

// smem byte offsets
#define SM_A32   0                          // 3 stages
#define SM_A16   (3 * A32_STAGE)            // 49152, 2 stages
#define SM_B16   (SM_A16 + 2 * A16_STAGE)   // 81920, 2 stages
#define SM_MBAR  (SM_B16 + 2 * B16_STAGE)   // 114688
#define SM_TOTAL (SM_MBAR + 128)            // 114816 = 112.1 KB -> 2 CTAs/SM

// post-mainloop overlays (inside dead A32 region)
#define OV_ES4   0                          // 4 x 128 floats
#define OV_PS    2048
#define OV_RED   2560
#define OV_CST   2688
#define OV_QS    4736
#define OV_VAS   5248

// mbar offsets within SM_MBAR
#define MB_FA(s)  ((s) * 8)                 // fullA32[3]
#define MB_EA(s)  (24 + (s) * 8)            // emptyA32[3]
#define MB_FB(s)  (48 + (s) * 8)            // fullB[2]
#define MB_EB(s)  (64 + (s) * 8)            // emptyB[2]

// ---------------- device scratch ----------------
__device__ float g_q[NB * HH];
__device__ float g_p[NB * LL];
__device__ float g_pz[NCTAS];
__device__ float g_pc[(size_t)NCTAS * QK];
__device__ int   g_cnt[NB];
__device__ __align__(128) uint8_t g_ub16[HH * QK * 2];   // packed fp16 Ua, pre-swizzled

// ---------------- helpers ----------------
__device__ __forceinline__ void mbar_init(uint32_t a, uint32_t cnt) {
    asm volatile("mbarrier.init.shared.b64 [%0], %1;" :: "r"(a), "r"(cnt) : "memory");
}
__device__ __forceinline__ void mbar_expect_tx(uint32_t a, uint32_t bytes) {
    asm volatile("mbarrier.arrive.expect_tx.shared.b64 _, [%0], %1;" :: "r"(a), "r"(bytes) : "memory");
}
__device__ __forceinline__ void mbar_arrive(uint32_t a) {
    asm volatile("mbarrier.arrive.shared.b64 _, [%0];" :: "r"(a) : "memory");
}
__device__ __forceinline__ void mbar_wait(uint32_t a, uint32_t par) {
    asm volatile(
        "{\n\t.reg .pred P1;\n"
        "WAIT_LOOP_%=:\n\t"
        "mbarrier.try_wait.parity.acquire.cta.shared::cta.b64 P1, [%0], %1, 0x989680;\n\t"
        "@P1 bra.uni WAIT_DONE_%=;\n\t"
        "bra.uni WAIT_LOOP_%=;\n"
        "WAIT_DONE_%=:\n\t}"
        :: "r"(a), "r"(par) : "memory");
}
__device__ __forceinline__ void tma2d(uint32_t dst, const CUtensorMap* m, int x, int y, uint32_t bar) {
    asm volatile(
        "cp.async.bulk.tensor.2d.shared::cta.global.tile.mbarrier::complete_tx::bytes "
        "[%0], [%1, {%2, %3}], [%4];"
        :: "r"(dst), "l"(m), "r"(x), "r"(y), "r"(bar) : "memory");
}
__device__ __forceinline__ void mma_f16(float* c, const uint32_t* a, const uint32_t* b) {
    asm volatile(
        "mma.sync.aligned.m16n8k16.row.col.f32.f16.f16.f32 "
        "{%0,%1,%2,%3},{%4,%5,%6,%7},{%8,%9},{%0,%1,%2,%3};"
        : "+f"(c[0]), "+f"(c[1]), "+f"(c[2]), "+f"(c[3])
        : "r"(a[0]), "r"(a[1]), "r"(a[2]), "r"(a[3]), "r"(b[0]), "r"(b[1]));
}
__device__ __forceinline__ void ldsm_x4(uint32_t& r0, uint32_t& r1, uint32_t& r2, uint32_t& r3,
                                        uint32_t addr) {
    asm volatile("ldmatrix.sync.aligned.m8n8.x4.shared.b16 {%0,%1,%2,%3}, [%4];"
                 : "=r"(r0), "=r"(r1), "=r"(r2), "=r"(r3) : "r"(addr));
}
__device__ __forceinline__ uint32_t cvt2h(float hi, float lo) {
    uint32_t d; asm("cvt.rn.f16x2.f32 %0, %1, %2;" : "=r"(d) : "f"(hi), "f"(lo)); return d;
}
__device__ __forceinline__ float tanh_fast(float x) {
    float y; asm("tanh.approx.f32 %0, %1;" : "=f"(y) : "f"(x)); return y;
}

// ---------------- kernel P: pack Ua -> fp16, chunk-major, pre-swizzled ----------------
// grid 128, block 256: one b32 (2 halves) per thread
__global__ void __launch_bounds__(256)
k_prep(const float* __restrict__ Ua) {
    int p  = blockIdx.x * 256 + threadIdx.x;    // 0..32767
    int h  = p >> 8;                             // Ua row
    int kl = (p & 255) * 2;                      // even k
    float f0 = Ua[h * QK + kl];
    float f1 = Ua[h * QK + kl + 1];
    uint32_t d = cvt2h(f1, f0);                  // halves (kl, kl+1) = (lo, hi)
    int bc  = kl >> 6;                           // big chunk
    int kll = kl & 63;                           // local half index
    int s   = kll >> 3;                          // 16B seg
    size_t addr = (size_t)bc * 16384 + h * 128 + ((s ^ (h & 7)) << 4) + (kll & 7) * 2;
    *reinterpret_cast<uint32_t*>(g_ub16 + addr) = d;
}

// ---------------- kernel 0: q projection ----------------
__global__ void __launch_bounds__(512)
k_qproj(const float* __restrict__ last_hidden, const float* __restrict__ Wa) {
    const int n    = blockIdx.x;
    const int warp = threadIdx.x >> 5;
    const int lane = threadIdx.x & 31;

    const float4* x4 = reinterpret_cast<const float4*>(last_hidden + (size_t)n * QK);
    float4 xv[4];
#pragma unroll
    for (int k = 0; k < 4; ++k) xv[k] = x4[lane + k * 32];

#pragma unroll
    for (int rr = 0; rr < 8; ++rr) {
        const int h = warp * 8 + rr;
        const float4* w4 = reinterpret_cast<const float4*>(Wa + (size_t)h * QK);
        float a = 0.f;
#pragma unroll
        for (int k = 0; k < 4; ++k) {
            float4 w = w4[lane + k * 32];
            a += w.x * xv[k].x + w.y * xv[k].y + w.z * xv[k].z + w.w * xv[k].w;
        }
#pragma unroll
        for (int o = 16; o > 0; o >>= 1) a += __shfl_xor_sync(0xffffffffu, a, o);
        if (lane == 0) g_q[n * HH + h] = a;
    }
}

// ---------------- kernel 1: fp16-MMA fused kernel ----------------
__global__ void __launch_bounds__(THREADS, 2)
k_fused(const __grid_constant__ CUtensorMap tmA,   // X fp32 tiles, SW128
        const __grid_constant__ CUtensorMap tmB,   // packed Ua fp16 blocks, SWIZZLE_NONE
        const float* __restrict__ X,               // (NB,LL,QK) for context re-read
        const float* __restrict__ va,              // (1,HH)
        float* __restrict__ out) {
    extern __shared__ __align__(1024) char sm[];
    const uint32_t su = (uint32_t)__cvta_generic_to_shared(sm);
    __shared__ int s_last;

    const int tid  = threadIdx.x;
    const int bx   = blockIdx.x;
    const int row0 = bx * ROWS_PER_CTA;
    const int n    = row0 >> 11;

    const int warp = tid >> 5;
    const int lane = tid & 31;
    const int wr = warp >> 2;          // warp-group 0/1 : 64-row strip
    const int wc = warp & 3;           // 0..3 : 32-col strip
    const int qt = warp & 3;           // conversion quarter within wg
    const int g  = lane >> 2;
    const int t  = lane & 3;

    // ldmatrix lane addressing (16B segs, XOR-swizzled 128B rows)
    const int swz7 = lane & 7;
    const int rowA = lane & 15;
    const int sxA  = lane >> 4;                       // 0/1 : k16 lo/hi seg
    const int rowB = (lane & 7) + ((lane >> 4) << 3); // j / j+1 row sel
    const int sxB  = (lane >> 3) & 1;

    const uint32_t mb = su + SM_MBAR;

    if (tid == 0) {
#pragma unroll
        for (int s = 0; s < 3; ++s) { mbar_init(mb + MB_FA(s), 1); mbar_init(mb + MB_EA(s), 8); }
#pragma unroll
        for (int s = 0; s < 2; ++s) { mbar_init(mb + MB_FB(s), 1); mbar_init(mb + MB_EB(s), 8); }
    }
    __syncthreads();

    // prologue: A32 chunks 0..2, B blocks 0..1
    if (tid == 0) {
#pragma unroll
        for (int c = 0; c < 3; ++c) {
            mbar_expect_tx(mb + MB_FA(c), A32_STAGE);
            tma2d(su + SM_A32 + c * A32_STAGE, &tmA, c * 32, row0, mb + MB_FA(c));
        }
#pragma unroll
        for (int b = 0; b < 2; ++b) {
            mbar_expect_tx(mb + MB_FB(b), B16_STAGE);
            tma2d(su + SM_B16 + b * B16_STAGE, &tmB, 0, b * 128, mb + MB_FB(b));
        }
    }

    float acc[4][4][4];
#pragma unroll
    for (int m = 0; m < 4; ++m)
#pragma unroll
        for (int j = 0; j < 4; ++j)
#pragma unroll
            for (int c = 0; c < 4; ++c) acc[m][j][c] = 0.f;

    const uint32_t aRow = su + SM_A16 + (uint32_t)((wr * 64 + rowA) * 128);
    const uint32_t bRow = su + SM_B16 + (uint32_t)((wc * 32 + rowB) * 128);

    // ---- mainloop over 8 big chunks ----
#pragma unroll 1
    for (int bc = 0; bc < NBIG; ++bc) {
        const int st16 = bc & 1;
        const uint32_t a16base = su + SM_A16 + st16 * A16_STAGE;

        // convert the two K32 sub-chunks into A16 stage (this warp's 16 rows each)
#pragma unroll
        for (int sub = 0; sub < 2; ++sub) {
            const int c = 2 * bc + sub;
            mbar_wait(mb + MB_FA(c % 3), (uint32_t)((c / 3) & 1));
            const uint32_t a32base = su + SM_A32 + (c % 3) * A32_STAGE;
#pragma unroll
            for (int i = 0; i < 4; ++i) {
                int v = lane + i * 32;
                int r = wr * 64 + qt * 16 + (v >> 3);
                int sa = v & 7;
                uint32_t srca = a32base + (uint32_t)(r * 128 + ((sa ^ (r & 7)) << 4));
                float f0, f1, f2, f3;
                asm volatile("ld.shared.v4.f32 {%0,%1,%2,%3}, [%4];"
                             : "=f"(f0), "=f"(f1), "=f"(f2), "=f"(f3) : "r"(srca));
                uint32_t h01 = cvt2h(f1, f0);
                uint32_t h23 = cvt2h(f3, f2);
                int s16 = sub * 4 + (sa >> 1);
                uint32_t dsta = a16base + (uint32_t)(r * 128 + ((s16 ^ (r & 7)) << 4) + (sa & 1) * 8);
                asm volatile("st.shared.v2.b32 [%0], {%1,%2};" :: "r"(dsta), "r"(h01), "r"(h23));
            }
        }
        if (lane == 0) {
            mbar_arrive(mb + MB_EA((2 * bc) % 3));
            mbar_arrive(mb + MB_EA((2 * bc + 1) % 3));
        }

        // producer: next A32 chunks (2bc+3, 2bc+4)
        if (tid == 0) {
#pragma unroll
            for (int d = 3; d <= 4; ++d) {
                int c = 2 * bc + d;
                if (c < NCH32) {
                    mbar_wait(mb + MB_EA(c % 3), (uint32_t)(((c - 3) / 3) & 1));
                    mbar_expect_tx(mb + MB_FA(c % 3), A32_STAGE);
                    tma2d(su + SM_A32 + (c % 3) * A32_STAGE, &tmA, c * 32, row0, mb + MB_FA(c % 3));
                }
            }
        }

        // warp-group rendezvous: A16 half written by these 4 warps is ready
        asm volatile("bar.sync %0, %1;" :: "r"(1 + wr), "r"(128) : "memory");

        mbar_wait(mb + MB_FB(st16), (uint32_t)((bc / 2) & 1));
        const uint32_t b16base = su + SM_B16 + st16 * B16_STAGE;
        const uint32_t aB = aRow + st16 * A16_STAGE - (su + SM_A16) + su + SM_A16; // aRow already has SM_A16
        (void)aB;

#pragma unroll
        for (int ks = 0; ks < 4; ++ks) {
            const uint32_t colA = (uint32_t)(((ks * 2 + sxA) ^ swz7) << 4);
            const uint32_t colB = (uint32_t)(((ks * 2 + sxB) ^ swz7) << 4);

            uint32_t bu[4][2];
#pragma unroll
            for (int jj = 0; jj < 2; ++jj) {
                ldsm_x4(bu[2*jj][0], bu[2*jj][1], bu[2*jj+1][0], bu[2*jj+1][1],
                        bRow + st16 * B16_STAGE + (uint32_t)(jj * 2048) + colB);
            }
#pragma unroll
            for (int m = 0; m < 4; ++m) {
                uint32_t au[4];
                ldsm_x4(au[0], au[1], au[2], au[3],
                        aRow + st16 * A16_STAGE + (uint32_t)(m * 2048) + colA);
#pragma unroll
                for (int j = 0; j < 4; ++j) mma_f16(acc[m][j], au, bu[j]);
            }
        }
        if (lane == 0) mbar_arrive(mb + MB_EB(st16));

        // producer: next B block bc+2
        if (tid == 0 && bc + 2 < NBIG) {
            mbar_wait(mb + MB_EB(st16), (uint32_t)((bc / 2) & 1));
            mbar_expect_tx(mb + MB_FB(st16), B16_STAGE);
            tma2d(su + SM_B16 + st16 * B16_STAGE, &tmB, 0, (bc + 2) * 128, mb + MB_FB(st16));
        }
    }

    // ---- all pipeline buffers dead after this sync; overlays become safe ----
    __syncthreads();
    float* es4 = reinterpret_cast<float*>(sm + OV_ES4);
    float* ps  = reinterpret_cast<float*>(sm + OV_PS);
    float* red = reinterpret_cast<float*>(sm + OV_RED);
    float* cst = reinterpret_cast<float*>(sm + OV_CST);
    float* qs  = reinterpret_cast<float*>(sm + OV_QS);
    float* vas = reinterpret_cast<float*>(sm + OV_VAS);

    if (tid < HH) {
        qs[tid]  = g_q[n * HH + tid];
        vas[tid] = va[tid];
    }
    __syncthreads();

    // ---- epilogue: e_r = sum_h va[h] * tanh(q[h] + C[r,h]) ----
#pragma unroll
    for (int m = 0; m < 4; ++m) {
#pragma unroll
        for (int rr = 0; rr < 2; ++rr) {
            float pa = 0.f;
#pragma unroll
            for (int j = 0; j < 4; ++j) {
#pragma unroll
                for (int cc = 0; cc < 2; ++cc) {
                    int h = wc * 32 + j * 8 + t * 2 + cc;
                    pa += vas[h] * tanh_fast(qs[h] + acc[m][j][rr * 2 + cc]);
                }
            }
            pa += __shfl_xor_sync(0xffffffffu, pa, 1);
            pa += __shfl_xor_sync(0xffffffffu, pa, 2);
            if (t == 0) es4[wc * 128 + wr * 64 + m * 16 + rr * 8 + g] = pa;
        }
    }
    __syncthreads();

    // energies bounded (|e| <= sum|va| ~= 11): exp without max-pass is safe
    if (tid < ROWS_PER_CTA) {
        float e = es4[tid] + es4[128 + tid] + es4[256 + tid] + es4[384 + tid];
        float p = __expf(e);
        ps[tid] = p;
        g_p[row0 + tid] = p;
        float s = p;
#pragma unroll
        for (int o = 16; o > 0; o >>= 1) s += __shfl_xor_sync(0xffffffffu, s, o);
        if (lane == 0) red[warp] = s;
    }
    __syncthreads();
    if (tid == 0) {
        float Z = 0.f;
#pragma unroll
        for (int i = 0; i < 4; ++i) Z += red[i];
        g_pz[bx] = Z;
    }
    __syncthreads();   // ps[] visible

    // ---- partial context: 2 row-halves of 64, then smem combine ----
    {
        const int c4 = (tid & 127) * 4;
        const int half = tid >> 7;
        const float* Xp = X + (size_t)(row0 + half * 64) * QK + c4;
        float4 a = make_float4(0.f, 0.f, 0.f, 0.f);
#pragma unroll 8
        for (int l = 0; l < 64; ++l) {
            float pl = ps[half * 64 + l];
            float4 x = *reinterpret_cast<const float4*>(Xp + (size_t)l * QK);
            a.x += pl * x.x; a.y += pl * x.y; a.z += pl * x.z; a.w += pl * x.w;
        }
        if (half == 1) *reinterpret_cast<float4*>(cst + c4) = a;
        __syncthreads();
        if (half == 0) {
            float4 b = *reinterpret_cast<const float4*>(cst + c4);
            a.x += b.x; a.y += b.y; a.z += b.z; a.w += b.w;
            *reinterpret_cast<float4*>(&g_pc[(size_t)bx * QK + c4]) = a;
        }
    }

    // ---- fan-in: last CTA of the batch combines ----
    __syncthreads();
    if (tid == 0) {
        __threadfence();
        int old = atomicAdd(&g_cnt[n], 1);
        s_last = (old == SPLITS - 1) ? 1 : 0;
    }
    __syncthreads();
    if (s_last) {
        __threadfence();
        float Z = 0.f;
#pragma unroll
        for (int i = 0; i < SPLITS; ++i) Z += g_pz[n * SPLITS + i];
        const float rZ = 1.f / Z;

        float* ctx = out;                       // (NB, QK)
        float* wts = out + (size_t)NB * QK;     // (NB, LL)
#pragma unroll
        for (int dd = 0; dd < QK / THREADS; ++dd) {
            int d = tid + dd * THREADS;
            float c = 0.f;
#pragma unroll
            for (int i = 0; i < SPLITS; ++i)
                c += g_pc[(size_t)(n * SPLITS + i) * QK + d];
            ctx[(size_t)n * QK + d] = c * rZ;
        }
#pragma unroll
        for (int i = 0; i < LL / THREADS; ++i) {
            int l = tid + i * THREADS;
            wts[(size_t)n * LL + l] = g_p[(size_t)n * LL + l] * rZ;
        }
        if (tid == 0) g_cnt[n] = 0;
    }
}

// ---------------- host: tensormap encode via runtime entry point ----------------
typedef CUresult (*tmap_encode_t)(
    CUtensorMap*, CUtensorMapDataType, cuuint32_t, void*,
    const cuuint64_t*, const cuuint64_t*, const cuuint32_t*, const cuuint32_t*,
    CUtensorMapInterleave, CUtensorMapSwizzle, CUtensorMapL2promotion, CUtensorMapFloatOOBfill);

extern "C" void kernel_launch(void* const* d_in, const int* in_sizes, int n_in,
                              void* d_out, int out_size) {
    const float* last_hidden     = (const float*)d_in[0];
    const float* encoder_outputs = (const float*)d_in[1];
    const float* Wa              = (const float*)d_in[2];
    const float* Ua              = (const float*)d_in[3];
    const float* va              = (const float*)d_in[4];
    float* out = (float*)d_out;

    static tmap_encode_t encode = nullptr;
    static void* ub16_dev = nullptr;
    static bool init_done = false;
    if (!init_done) {
        cudaFuncSetAttribute(k_fused, cudaFuncAttributeMaxDynamicSharedMemorySize, SM_TOTAL);
        cudaDriverEntryPointQueryResult qr;
        void* fp = nullptr;
        cudaGetDriverEntryPoint("cuTensorMapEncodeTiled", &fp, cudaEnableDefault, &qr);
        encode = (tmap_encode_t)fp;
        cudaGetSymbolAddress(&ub16_dev, g_ub16);
        init_done = true;
    }

    CUtensorMap tmA, tmB;
    {   // X fp32: rows NB*LL x 512 floats; box 32x128, SW128
        cuuint64_t dims[2]   = {QK, (cuuint64_t)NB * LL};
        cuuint64_t stride[1] = {QK * sizeof(float)};
        cuuint32_t box[2]    = {32, ROWS_PER_CTA};
        cuuint32_t elems[2]  = {1, 1};
        encode(&tmA, CU_TENSOR_MAP_DATA_TYPE_FLOAT32, 2, (void*)encoder_outputs,
               dims, stride, box, elems,
               CU_TENSOR_MAP_INTERLEAVE_NONE, CU_TENSOR_MAP_SWIZZLE_128B,
               CU_TENSOR_MAP_L2_PROMOTION_L2_128B, CU_TENSOR_MAP_FLOAT_OOB_FILL_NONE);
    }
    {   // packed Ua fp16: 1024 rows of 64 halves (swizzle pre-baked); box 64x128, no TMA swizzle
        cuuint64_t dims[2]   = {64, 1024};
        cuuint64_t stride[1] = {128};
        cuuint32_t box[2]    = {64, 128};
        cuuint32_t elems[2]  = {1, 1};
        encode(&tmB, CU_TENSOR_MAP_DATA_TYPE_UINT16, 2, ub16_dev,
               dims, stride, box, elems,
               CU_TENSOR_MAP_INTERLEAVE_NONE, CU_TENSOR_MAP_SWIZZLE_NONE,
               CU_TENSOR_MAP_L2_PROMOTION_L2_128B, CU_TENSOR_MAP_FLOAT_OOB_FILL_NONE);
    }

    k_prep<<<128, 256>>>(Ua);
    k_qproj<<<NB, 512>>>(last_hidden, Wa);
    k_fused<<<NCTAS, THREADS, SM_TOTAL>>>(tmA, tmB, encoder_outputs, va, out);
}

// round 12
// speedup vs baseline: 1.2043x; 1.2043x over previous
#include <cuda_runtime.h>
#include <cuda.h>
#include <cstdint>

// Problem dims (fixed)
#define NB   256
#define LL   2048
#define QK   512
#define HH   128

#define TILE_ROWS 128
#define SPLITS    16                        // per batch
#define NCTAS     2048                      // each CTA: 2 tiles = 256 rows
#define THREADS   256
#define NSTAGE    3
#define NCH       32                        // 2 tiles x 16 K32-chunks

#define A_STAGE_BYTES 16384                 // 128 rows x 128B fp32 (K=32)
#define B_STAGE_BYTES 16384
#define STAGE_TX      (A_STAGE_BYTES + B_STAGE_BYTES)

// smem byte offsets
#define SM_A     0                          // 3 stages
#define SM_B     (3 * A_STAGE_BYTES)        // 49152, 3 stages
#define SM_QS    (SM_B + 3 * B_STAGE_BYTES) // 98304
#define SM_VAS   (SM_QS + 512)              // 98816
#define SM_ES0   (SM_VAS + 512)             // 99328
#define SM_ES1   (SM_ES0 + 2048)            // 101376
#define SM_PS0   (SM_ES1 + 2048)            // 103424
#define SM_PS1   (SM_PS0 + 512)             // 103936
#define SM_RED0  (SM_PS1 + 512)             // 104448
#define SM_RED1  (SM_RED0 + 128)            // 104576
#define SM_CST   (SM_RED1 + 128)            // 104704
#define SM_MBAR  (SM_CST + 2048)            // 106752
#define SM_TOTAL (SM_MBAR + 64)             // 106816 = 104.3 KB -> 2 CTAs/SM

// ---------------- device scratch ----------------
__device__ float g_q[NB * HH];
__device__ float g_p[NB * LL];
__device__ float g_pz[NB * SPLITS];
__device__ float g_pc[(size_t)NB * SPLITS * QK];
__device__ int   g_cnt[NB];                 // zero-init; self-resetting

// ---------------- helpers ----------------
__device__ __forceinline__ void mbar_init(uint32_t a, uint32_t cnt) {
    asm volatile("mbarrier.init.shared.b64 [%0], %1;" :: "r"(a), "r"(cnt) : "memory");
}
__device__ __forceinline__ void mbar_expect_tx(uint32_t a, uint32_t bytes) {
    asm volatile("mbarrier.arrive.expect_tx.shared.b64 _, [%0], %1;" :: "r"(a), "r"(bytes) : "memory");
}
__device__ __forceinline__ void mbar_arrive(uint32_t a) {
    asm volatile("mbarrier.arrive.shared.b64 _, [%0];" :: "r"(a) : "memory");
}
__device__ __forceinline__ void mbar_wait(uint32_t a, uint32_t par) {
    asm volatile(
        "{\n\t.reg .pred P1;\n"
        "WAIT_LOOP_%=:\n\t"
        "mbarrier.try_wait.parity.acquire.cta.shared::cta.b64 P1, [%0], %1, 0x989680;\n\t"
        "@P1 bra.uni WAIT_DONE_%=;\n\t"
        "bra.uni WAIT_LOOP_%=;\n"
        "WAIT_DONE_%=:\n\t}"
        :: "r"(a), "r"(par) : "memory");
}
__device__ __forceinline__ void tma2d(uint32_t dst, const CUtensorMap* m, int x, int y, uint32_t bar) {
    asm volatile(
        "cp.async.bulk.tensor.2d.shared::cta.global.tile.mbarrier::complete_tx::bytes "
        "[%0], [%1, {%2, %3}], [%4];"
        :: "r"(dst), "l"(m), "r"(x), "r"(y), "r"(bar) : "memory");
}
__device__ __forceinline__ void mma_tf32(float* c, const uint32_t* a, const uint32_t* b) {
    asm volatile(
        "mma.sync.aligned.m16n8k8.row.col.f32.tf32.tf32.f32 "
        "{%0,%1,%2,%3},{%4,%5,%6,%7},{%8,%9},{%0,%1,%2,%3};"
        : "+f"(c[0]), "+f"(c[1]), "+f"(c[2]), "+f"(c[3])
        : "r"(a[0]), "r"(a[1]), "r"(a[2]), "r"(a[3]), "r"(b[0]), "r"(b[1]));
}
__device__ __forceinline__ void ldsm_x4(uint32_t& r0, uint32_t& r1, uint32_t& r2, uint32_t& r3,
                                        uint32_t addr) {
    asm volatile("ldmatrix.sync.aligned.m8n8.x4.shared.b16 {%0,%1,%2,%3}, [%4];"
                 : "=r"(r0), "=r"(r1), "=r"(r2), "=r"(r3) : "r"(addr));
}
__device__ __forceinline__ float tanh_fast(float x) {
    float y; asm("tanh.approx.f32 %0, %1;" : "=f"(y) : "f"(x)); return y;
}
__device__ __forceinline__ void bar_named(int id, int cnt) {
    asm volatile("bar.sync %0, %1;" :: "r"(id), "r"(cnt) : "memory");
}

// ---------------- kernel 0: q projection (coalesced, warp-per-rows) ----------------
__global__ void __launch_bounds__(512)
k_qproj(const float* __restrict__ last_hidden, const float* __restrict__ Wa) {
    const int n    = blockIdx.x;
    const int warp = threadIdx.x >> 5;
    const int lane = threadIdx.x & 31;

    const float4* x4 = reinterpret_cast<const float4*>(last_hidden + (size_t)n * QK);
    float4 xv[4];
#pragma unroll
    for (int k = 0; k < 4; ++k) xv[k] = x4[lane + k * 32];

#pragma unroll
    for (int rr = 0; rr < 8; ++rr) {
        const int h = warp * 8 + rr;
        const float4* w4 = reinterpret_cast<const float4*>(Wa + (size_t)h * QK);
        float a = 0.f;
#pragma unroll
        for (int k = 0; k < 4; ++k) {
            float4 w = w4[lane + k * 32];
            a += w.x * xv[k].x + w.y * xv[k].y + w.z * xv[k].z + w.w * xv[k].w;
        }
#pragma unroll
        for (int o = 16; o > 0; o >>= 1) a += __shfl_xor_sync(0xffffffffu, a, o);
        if (lane == 0) g_q[n * HH + h] = a;
    }
}

// ---------------- kernel 1: persistent 2-tile, TMA-fed, warp-split tail ----------------
__global__ void __launch_bounds__(THREADS, 2)
k_fused(const __grid_constant__ CUtensorMap tmA,   // X tiles, SW128
        const __grid_constant__ CUtensorMap tmB,   // Ua tiles, SW128
        const float* __restrict__ X,               // (NB,LL,QK) for context re-read
        const float* __restrict__ va,              // (1,HH)
        float* __restrict__ out) {
    extern __shared__ __align__(1024) char sm[];
    const uint32_t su = (uint32_t)__cvta_generic_to_shared(sm);
    float* qs   = reinterpret_cast<float*>(sm + SM_QS);
    float* vas  = reinterpret_cast<float*>(sm + SM_VAS);
    float* es0  = reinterpret_cast<float*>(sm + SM_ES0);
    float* es1  = reinterpret_cast<float*>(sm + SM_ES1);
    float* ps0  = reinterpret_cast<float*>(sm + SM_PS0);
    float* ps1  = reinterpret_cast<float*>(sm + SM_PS1);
    float* red0 = reinterpret_cast<float*>(sm + SM_RED0);
    float* red1 = reinterpret_cast<float*>(sm + SM_RED1);
    float* cst  = reinterpret_cast<float*>(sm + SM_CST);
    __shared__ int s_last1;

    const int tid  = threadIdx.x;
    const int bx   = blockIdx.x;
    const int rowA = bx * 256;                 // tile0 rows [rowA, rowA+128)
    const int n    = bx >> 3;                  // batch
    const int sx0  = bx * 2;                   // global split index of tile0

    const int warp = tid >> 5;
    const int lane = tid & 31;
    const int wr = warp >> 2;          // 0..1 : 64-row strip
    const int wc = warp & 3;           // 0..3 : 32-col strip
    const int g  = lane >> 2;
    const int t  = lane & 3;

    // ldmatrix lane addressing (16B segs, SW128-swizzled 128B rows)
    const int swz  = (lane & 7) << 4;
    const int rowAa = lane & 15;
    const int hiA  = (lane >> 4) << 4;
    const int rowBb = (lane & 7) + ((lane >> 4) << 3);
    const int hiB  = ((lane >> 3) & 1) << 4;

    const uint32_t mbf = su + SM_MBAR;        // full[s] at +s*8
    const uint32_t mbe = su + SM_MBAR + 24;   // empty[s] at +s*8

    if (tid == 0) {
#pragma unroll
        for (int s = 0; s < NSTAGE; ++s) {
            mbar_init(mbf + s * 8, 1);
            mbar_init(mbe + s * 8, 8);
        }
    }
    if (tid < HH) {
        vas[tid] = va[tid];
        qs[tid]  = g_q[n * HH + tid];
    }
    __syncthreads();

    // prologue: chunks 0,1 in flight
    if (tid == 0) {
        mbar_expect_tx(mbf + 0, STAGE_TX);
        tma2d(su + SM_A, &tmA, 0, rowA, mbf + 0);
        tma2d(su + SM_B, &tmB, 0, 0, mbf + 0);
        mbar_expect_tx(mbf + 8, STAGE_TX);
        tma2d(su + SM_A + A_STAGE_BYTES, &tmA, 32, rowA, mbf + 8);
        tma2d(su + SM_B + B_STAGE_BYTES, &tmB, 32, 0, mbf + 8);
    }

    float acc[4][4][4];
#pragma unroll
    for (int m = 0; m < 4; ++m)
#pragma unroll
        for (int j = 0; j < 4; ++j)
#pragma unroll
            for (int c = 0; c < 4; ++c) acc[m][j][c] = 0.f;

    const uint32_t a_tile_off = (uint32_t)((wr * 64 + rowAa) * 128);
    const uint32_t b_tile_off = (uint32_t)((wc * 32 + rowBb) * 128);

    // ---- 32-chunk mainloop across both tiles ----
#pragma unroll 1
    for (int kc = 0; kc < NCH; ++kc) {
        const int s = kc % NSTAGE;
        const int phase = (kc / NSTAGE) & 1;

        // producer: chunk kc+2
        if (tid == 0 && kc + 2 < NCH) {
            const int c  = kc + 2;
            const int ns = c % NSTAGE;
            if (c >= NSTAGE)
                mbar_wait(mbe + ns * 8, (uint32_t)(((c - NSTAGE) / NSTAGE) & 1));
            mbar_expect_tx(mbf + ns * 8, STAGE_TX);
            tma2d(su + SM_A + ns * A_STAGE_BYTES, &tmA, (c & 15) * 32,
                  rowA + (c >> 4) * TILE_ROWS, mbf + ns * 8);
            tma2d(su + SM_B + ns * B_STAGE_BYTES, &tmB, (c & 15) * 32, 0, mbf + ns * 8);
        }

        mbar_wait(mbf + s * 8, (uint32_t)phase);

        const uint32_t ab = su + SM_A + s * A_STAGE_BYTES + a_tile_off;
        const uint32_t bb = su + SM_B + s * B_STAGE_BYTES + b_tile_off;

#pragma unroll
        for (int ks = 0; ks < 4; ++ks) {
            const uint32_t colA = (uint32_t)((ks * 32 + hiA) ^ swz);
            const uint32_t colB = (uint32_t)((ks * 32 + hiB) ^ swz);

            uint32_t bu[4][2];
#pragma unroll
            for (int jj = 0; jj < 2; ++jj) {
                ldsm_x4(bu[2*jj][0], bu[2*jj][1], bu[2*jj+1][0], bu[2*jj+1][1],
                        bb + (uint32_t)(jj * 16 * 128) + colB);
            }
#pragma unroll
            for (int m = 0; m < 4; ++m) {
                uint32_t au[4];
                ldsm_x4(au[0], au[1], au[2], au[3],
                        ab + (uint32_t)(m * 16 * 128) + colA);
#pragma unroll
                for (int j = 0; j < 4; ++j) mma_tf32(acc[m][j], au, bu[j]);
            }
        }
        if (lane == 0) mbar_arrive(mbe + s * 8);

        // ---- tile boundary: tile0 epilogue; warps 4-7 take the tail ----
        if (kc == 15) {
#pragma unroll
            for (int m = 0; m < 4; ++m) {
#pragma unroll
                for (int rr = 0; rr < 2; ++rr) {
                    float pa = 0.f;
#pragma unroll
                    for (int j = 0; j < 4; ++j) {
#pragma unroll
                        for (int cc = 0; cc < 2; ++cc) {
                            int h = wc * 32 + j * 8 + t * 2 + cc;
                            pa += vas[h] * tanh_fast(qs[h] + acc[m][j][rr * 2 + cc]);
                        }
                    }
                    pa += __shfl_xor_sync(0xffffffffu, pa, 1);
                    pa += __shfl_xor_sync(0xffffffffu, pa, 2);
                    if (t == 0) es0[wc * 128 + wr * 64 + m * 16 + rr * 8 + g] = pa;
#pragma unroll
                    for (int j = 0; j < 4; ++j)
#pragma unroll
                        for (int cc = 0; cc < 2; ++cc)
                            acc[m][j][rr * 2 + cc] = 0.f;
                }
            }
            __syncthreads();    // es0 visible; fast warps continue, slow warps do tail

            if (tid >= 128) {
                // ======= tile0 tail (warps 4-7, 128 threads, bar 3) =======
                const int idx = tid - 128;
                float e = es0[idx] + es0[128 + idx] + es0[256 + idx] + es0[384 + idx];
                float p = __expf(e);          // energies bounded: no max-pass needed
                ps0[idx] = p;
                g_p[rowA + idx] = p;
                float sZ = p;
#pragma unroll
                for (int o = 16; o > 0; o >>= 1) sZ += __shfl_xor_sync(0xffffffffu, sZ, o);
                if (lane == 0) red0[warp - 4] = sZ;
                bar_named(3, 128);            // ps0 + red0 visible to tail group
                if (idx == 0)
                    g_pz[sx0] = red0[0] + red0[1] + red0[2] + red0[3];

                // context GEMV: thread owns 4 cols, all 128 rows (L2 re-read)
                const float* Xp = X + (size_t)rowA * QK + idx * 4;
                float4 a = make_float4(0.f, 0.f, 0.f, 0.f);
#pragma unroll 8
                for (int l = 0; l < 128; ++l) {
                    float pl = ps0[l];
                    float4 x = *reinterpret_cast<const float4*>(Xp + (size_t)l * QK);
                    a.x += pl * x.x; a.y += pl * x.y; a.z += pl * x.z; a.w += pl * x.w;
                }
                *reinterpret_cast<float4*>(&g_pc[(size_t)sx0 * QK + idx * 4]) = a;

                bar_named(3, 128);
                if (idx == 0) {
                    __threadfence();
                    atomicAdd(&g_cnt[n], 1);  // tile0 can never be the 16th arrival
                }
                // ======= end tile0 tail =======
            }
        }
    }

    // ---- tile1 epilogue (all warps) ----
#pragma unroll
    for (int m = 0; m < 4; ++m) {
#pragma unroll
        for (int rr = 0; rr < 2; ++rr) {
            float pa = 0.f;
#pragma unroll
            for (int j = 0; j < 4; ++j) {
#pragma unroll
                for (int cc = 0; cc < 2; ++cc) {
                    int h = wc * 32 + j * 8 + t * 2 + cc;
                    pa += vas[h] * tanh_fast(qs[h] + acc[m][j][rr * 2 + cc]);
                }
            }
            pa += __shfl_xor_sync(0xffffffffu, pa, 1);
            pa += __shfl_xor_sync(0xffffffffu, pa, 2);
            if (t == 0) es1[wc * 128 + wr * 64 + m * 16 + rr * 8 + g] = pa;
        }
    }
    __syncthreads();

    const int rowB0 = rowA + 128;
    if (tid < 128) {
        float e = es1[tid] + es1[128 + tid] + es1[256 + tid] + es1[384 + tid];
        float p = __expf(e);
        ps1[tid] = p;
        g_p[rowB0 + tid] = p;
        float sZ = p;
#pragma unroll
        for (int o = 16; o > 0; o >>= 1) sZ += __shfl_xor_sync(0xffffffffu, sZ, o);
        if (lane == 0) red1[warp] = sZ;
    }
    __syncthreads();
    if (tid == 0)
        g_pz[sx0 + 1] = red1[0] + red1[1] + red1[2] + red1[3];
    __syncthreads();   // ps1 visible

    // context: 2 row-halves of 64, smem combine (256 threads)
    {
        const int c4 = (tid & 127) * 4;
        const int half = tid >> 7;
        const float* Xp = X + (size_t)(rowB0 + half * 64) * QK + c4;
        float4 a = make_float4(0.f, 0.f, 0.f, 0.f);
#pragma unroll 8
        for (int l = 0; l < 64; ++l) {
            float pl = ps1[half * 64 + l];
            float4 x = *reinterpret_cast<const float4*>(Xp + (size_t)l * QK);
            a.x += pl * x.x; a.y += pl * x.y; a.z += pl * x.z; a.w += pl * x.w;
        }
        if (half == 1) *reinterpret_cast<float4*>(cst + c4) = a;
        __syncthreads();
        if (half == 0) {
            float4 b = *reinterpret_cast<const float4*>(cst + c4);
            a.x += b.x; a.y += b.y; a.z += b.z; a.w += b.w;
            *reinterpret_cast<float4*>(&g_pc[(size_t)(sx0 + 1) * QK + c4]) = a;
        }
    }

    // ---- fan-in: tile1 arrival; combine when all 16 splits done ----
    __syncthreads();
    if (tid == 0) {
        __threadfence();
        int old = atomicAdd(&g_cnt[n], 1);
        s_last1 = (old == SPLITS - 1) ? 1 : 0;
    }
    __syncthreads();
    if (s_last1) {
        __threadfence();
        float Z = 0.f;
#pragma unroll
        for (int i = 0; i < SPLITS; ++i) Z += g_pz[n * SPLITS + i];
        const float rZ = 1.f / Z;

        float* ctx = out;                       // (NB, QK)
        float* wts = out + (size_t)NB * QK;     // (NB, LL)
#pragma unroll
        for (int dd = 0; dd < QK / THREADS; ++dd) {
            int d = tid + dd * THREADS;
            float c = 0.f;
#pragma unroll
            for (int i = 0; i < SPLITS; ++i)
                c += g_pc[(size_t)(n * SPLITS + i) * QK + d];
            ctx[(size_t)n * QK + d] = c * rZ;
        }
#pragma unroll
        for (int i = 0; i < LL / THREADS; ++i) {
            int l = tid + i * THREADS;
            wts[(size_t)n * LL + l] = g_p[(size_t)n * LL + l] * rZ;
        }
        if (tid == 0) g_cnt[n] = 0;   // self-reset for next replay
    }
}

// ---------------- host: tensormap encode via runtime entry point (no -lcuda) ----------------
typedef CUresult (*tmap_encode_t)(
    CUtensorMap*, CUtensorMapDataType, cuuint32_t, void*,
    const cuuint64_t*, const cuuint64_t*, const cuuint32_t*, const cuuint32_t*,
    CUtensorMapInterleave, CUtensorMapSwizzle, CUtensorMapL2promotion, CUtensorMapFloatOOBfill);

extern "C" void kernel_launch(void* const* d_in, const int* in_sizes, int n_in,
                              void* d_out, int out_size) {
    const float* last_hidden     = (const float*)d_in[0];
    const float* encoder_outputs = (const float*)d_in[1];
    const float* Wa              = (const float*)d_in[2];
    const float* Ua              = (const float*)d_in[3];
    const float* va              = (const float*)d_in[4];
    float* out = (float*)d_out;

    static tmap_encode_t encode = nullptr;
    static bool attr_set = false;
    if (!attr_set) {
        cudaFuncSetAttribute(k_fused, cudaFuncAttributeMaxDynamicSharedMemorySize, SM_TOTAL);
        cudaDriverEntryPointQueryResult qr;
        void* fp = nullptr;
        cudaGetDriverEntryPoint("cuTensorMapEncodeTiled", &fp, cudaEnableDefault, &qr);
        encode = (tmap_encode_t)fp;
        attr_set = true;
    }

    CUtensorMap tmA, tmB;
    {   // X fp32: (NB*LL) x 512 floats; box 32x128, SW128
        cuuint64_t dims[2]   = {QK, (cuuint64_t)NB * LL};
        cuuint64_t stride[1] = {QK * sizeof(float)};
        cuuint32_t box[2]    = {32, TILE_ROWS};
        cuuint32_t elems[2]  = {1, 1};
        encode(&tmA, CU_TENSOR_MAP_DATA_TYPE_FLOAT32, 2, (void*)encoder_outputs,
               dims, stride, box, elems,
               CU_TENSOR_MAP_INTERLEAVE_NONE, CU_TENSOR_MAP_SWIZZLE_128B,
               CU_TENSOR_MAP_L2_PROMOTION_L2_128B, CU_TENSOR_MAP_FLOAT_OOB_FILL_NONE);
    }
    {   // Ua fp32: 128 x 512 floats; box 32x128, SW128
        cuuint64_t dims[2]   = {QK, HH};
        cuuint64_t stride[1] = {QK * sizeof(float)};
        cuuint32_t box[2]    = {32, HH};
        cuuint32_t elems[2]  = {1, 1};
        encode(&tmB, CU_TENSOR_MAP_DATA_TYPE_FLOAT32, 2, (void*)Ua,
               dims, stride, box, elems,
               CU_TENSOR_MAP_INTERLEAVE_NONE, CU_TENSOR_MAP_SWIZZLE_128B,
               CU_TENSOR_MAP_L2_PROMOTION_L2_128B, CU_TENSOR_MAP_FLOAT_OOB_FILL_NONE);
    }

    k_qproj<<<NB, 512>>>(last_hidden, Wa);
    k_fused<<<NCTAS, THREADS, SM_TOTAL>>>(tmA, tmB, encoder_outputs, va, out);
}

// round 13
// speedup vs baseline: 1.3288x; 1.1033x over previous
#include <cuda_runtime.h>
#include <cuda.h>
#include <cstdint>

// Problem dims (fixed)
#define NB   256
#define LL   2048
#define QK   512
#define HH   128

#define ROWS_PER_CTA 128
#define SPLITS       (LL / ROWS_PER_CTA)    // 16
#define NCTAS        (NB * SPLITS)          // 4096
#define KCHUNK       32                     // floats -> 128B rows (SW128 atom)
#define NCHUNKS      (QK / KCHUNK)          // 16
#define THREADS      256
#define NSTAGE       3

#define A_STAGE_BYTES 16384                 // 128 rows x 128B
#define B_STAGE_BYTES 16384                 // 128 rows x 128B
#define STAGE_TX      (A_STAGE_BYTES + B_STAGE_BYTES)

// smem byte offsets
#define SM_A     0
#define SM_B     (NSTAGE * A_STAGE_BYTES)              // 49152
#define SM_QS    (SM_B + NSTAGE * B_STAGE_BYTES)       // 98304
#define SM_VAS   (SM_QS + 512)                         // 98816
#define SM_ES4   (SM_VAS + 512)                        // 99328: 4 x 128 floats
#define SM_PS    (SM_ES4 + 2048)                       // 101376
#define SM_RED   (SM_PS + 512)                         // 101888
#define SM_CST   (SM_RED + 128)                        // 102016: 1 partial ctx slice
#define SM_MBAR  (SM_CST + 2048)                       // 104064: full[3] + empty[3]
#define SM_TOTAL (SM_MBAR + 64)                        // ~101.7 KB -> 2 CTAs/SM

// ---------------- device scratch ----------------
__device__ float g_q[NB * HH];              // q = Wa @ last_hidden
__device__ float g_p[NB * LL];
__device__ float g_pz[NCTAS];
__device__ float g_pc[(size_t)NCTAS * QK];
__device__ int   g_cnt[NB];                 // zero-init; self-resetting

// ---------------- helpers ----------------
__device__ __forceinline__ void mbar_init(uint32_t a, uint32_t cnt) {
    asm volatile("mbarrier.init.shared.b64 [%0], %1;" :: "r"(a), "r"(cnt) : "memory");
}
__device__ __forceinline__ void mbar_expect_tx(uint32_t a, uint32_t bytes) {
    asm volatile("mbarrier.arrive.expect_tx.shared.b64 _, [%0], %1;" :: "r"(a), "r"(bytes) : "memory");
}
__device__ __forceinline__ void mbar_arrive(uint32_t a) {
    asm volatile("mbarrier.arrive.shared.b64 _, [%0];" :: "r"(a) : "memory");
}
__device__ __forceinline__ void mbar_wait(uint32_t a, uint32_t par) {
    asm volatile(
        "{\n\t.reg .pred P1;\n"
        "WAIT_LOOP_%=:\n\t"
        "mbarrier.try_wait.parity.acquire.cta.shared::cta.b64 P1, [%0], %1, 0x989680;\n\t"
        "@P1 bra.uni WAIT_DONE_%=;\n\t"
        "bra.uni WAIT_LOOP_%=;\n"
        "WAIT_DONE_%=:\n\t}"
        :: "r"(a), "r"(par) : "memory");
}
__device__ __forceinline__ void tma2d(uint32_t dst, const CUtensorMap* m, int x, int y, uint32_t bar) {
    asm volatile(
        "cp.async.bulk.tensor.2d.shared::cta.global.tile.mbarrier::complete_tx::bytes "
        "[%0], [%1, {%2, %3}], [%4];"
        :: "r"(dst), "l"(m), "r"(x), "r"(y), "r"(bar) : "memory");
}
__device__ __forceinline__ void mma_tf32(float* c, const uint32_t* a, const uint32_t* b) {
    asm volatile(
        "mma.sync.aligned.m16n8k8.row.col.f32.tf32.tf32.f32 "
        "{%0,%1,%2,%3},{%4,%5,%6,%7},{%8,%9},{%0,%1,%2,%3};"
        : "+f"(c[0]), "+f"(c[1]), "+f"(c[2]), "+f"(c[3])
        : "r"(a[0]), "r"(a[1]), "r"(a[2]), "r"(a[3]), "r"(b[0]), "r"(b[1]));
}
__device__ __forceinline__ void ldsm_x4(uint32_t& r0, uint32_t& r1, uint32_t& r2, uint32_t& r3,
                                        uint32_t addr) {
    asm volatile("ldmatrix.sync.aligned.m8n8.x4.shared.b16 {%0,%1,%2,%3}, [%4];"
                 : "=r"(r0), "=r"(r1), "=r"(r2), "=r"(r3) : "r"(addr));
}
__device__ __forceinline__ float tanh_fast(float x) {
    float y; asm("tanh.approx.f32 %0, %1;" : "=f"(y) : "f"(x)); return y;
}

// ---------------- kernel 0: q projection (coalesced, warp-per-rows) ----------------
__global__ void __launch_bounds__(512)
k_qproj(const float* __restrict__ last_hidden, const float* __restrict__ Wa) {
    const int n    = blockIdx.x;
    const int warp = threadIdx.x >> 5;
    const int lane = threadIdx.x & 31;

    const float4* x4 = reinterpret_cast<const float4*>(last_hidden + (size_t)n * QK);
    float4 xv[4];
#pragma unroll
    for (int k = 0; k < 4; ++k) xv[k] = x4[lane + k * 32];

#pragma unroll
    for (int rr = 0; rr < 8; ++rr) {
        const int h = warp * 8 + rr;
        const float4* w4 = reinterpret_cast<const float4*>(Wa + (size_t)h * QK);
        float a = 0.f;
#pragma unroll
        for (int k = 0; k < 4; ++k) {
            float4 w = w4[lane + k * 32];
            a += w.x * xv[k].x + w.y * xv[k].y + w.z * xv[k].z + w.w * xv[k].w;
        }
#pragma unroll
        for (int o = 16; o > 0; o >>= 1) a += __shfl_xor_sync(0xffffffffu, a, o);
        if (lane == 0) g_q[n * HH + h] = a;
    }
}

// ---------------- kernel 1: TMA-fed, full/empty pipeline, fragment double-buffer ----------------
__global__ void __launch_bounds__(THREADS, 2)
k_fused(const __grid_constant__ CUtensorMap tmA,   // X tiles, SW128
        const __grid_constant__ CUtensorMap tmB,   // Ua tiles, SW128
        const float* __restrict__ X,               // (NB,LL,QK) for context re-read
        const float* __restrict__ va,              // (1,HH)
        float* __restrict__ out) {
    extern __shared__ __align__(1024) char sm[];
    const uint32_t su = (uint32_t)__cvta_generic_to_shared(sm);
    float* qs  = reinterpret_cast<float*>(sm + SM_QS);
    float* vas = reinterpret_cast<float*>(sm + SM_VAS);
    float* es4 = reinterpret_cast<float*>(sm + SM_ES4);
    float* ps  = reinterpret_cast<float*>(sm + SM_PS);
    float* red = reinterpret_cast<float*>(sm + SM_RED);
    float* cst = reinterpret_cast<float*>(sm + SM_CST);
    __shared__ int s_last;

    const int tid  = threadIdx.x;
    const int bx   = blockIdx.x;
    const int row0 = bx * ROWS_PER_CTA;
    const int n    = row0 >> 11;              // row0 / 2048

    const int warp = tid >> 5;
    const int lane = tid & 31;
    const int wr = warp >> 2;          // 0..1 : 64-row strip
    const int wc = warp & 3;           // 0..3 : 32-col strip
    const int g  = lane >> 2;
    const int t  = lane & 3;

    // ldmatrix per-lane addressing (16B segments, SW128-swizzled rows)
    const int swz  = (lane & 7) << 4;
    const int rowA = lane & 15;
    const int hiA  = (lane >> 4) << 4;
    const int rowB = (lane & 7) + ((lane >> 4) << 3);
    const int hiB  = ((lane >> 3) & 1) << 4;

    // per-ks swizzled column offsets (constants, hoisted)
    uint32_t colA[4], colB[4];
#pragma unroll
    for (int ks = 0; ks < 4; ++ks) {
        colA[ks] = (uint32_t)((ks * 32 + hiA) ^ swz);
        colB[ks] = (uint32_t)((ks * 32 + hiB) ^ swz);
    }

    const uint32_t mbf = su + SM_MBAR;        // full[s] at +s*8
    const uint32_t mbe = su + SM_MBAR + 24;   // empty[s] at +s*8

    if (tid == 0) {
#pragma unroll
        for (int s = 0; s < NSTAGE; ++s) {
            mbar_init(mbf + s * 8, 1);     // flipped by expect_tx + TMA complete
            mbar_init(mbe + s * 8, 8);     // flipped by 8 warp arrivals
        }
    }
    if (tid < HH) {
        vas[tid] = va[tid];
        qs[tid]  = g_q[n * HH + tid];
    }
    __syncthreads();   // mbarrier init + qs visible

    // prologue: 2 chunks in flight (buffers empty at start -> no empty-wait)
    if (tid == 0) {
        mbar_expect_tx(mbf + 0, STAGE_TX);
        tma2d(su + SM_A, &tmA, 0, row0, mbf + 0);
        tma2d(su + SM_B, &tmB, 0, 0, mbf + 0);
        mbar_expect_tx(mbf + 8, STAGE_TX);
        tma2d(su + SM_A + A_STAGE_BYTES, &tmA, KCHUNK, row0, mbf + 8);
        tma2d(su + SM_B + B_STAGE_BYTES, &tmB, KCHUNK, 0, mbf + 8);
    }

    float acc[4][4][4];
#pragma unroll
    for (int m = 0; m < 4; ++m)
#pragma unroll
        for (int j = 0; j < 4; ++j)
#pragma unroll
            for (int c = 0; c < 4; ++c) acc[m][j][c] = 0.f;

    const uint32_t a_tile_off = (uint32_t)((wr * 64 + rowA) * 128);
    const uint32_t b_tile_off = (uint32_t)((wc * 32 + rowB) * 128);

    // ---- mainloop: per-warp full/empty protocol + fragment double-buffering ----
#pragma unroll 1
    for (int kc = 0; kc < NCHUNKS; ++kc) {
        const int s = kc - (kc / NSTAGE) * NSTAGE;      // kc % 3
        const int phase = (kc / NSTAGE) & 1;

        // producer: issue chunk kc+2 into its stage after that stage drains
        if (tid == 0 && kc + 2 < NCHUNKS) {
            const int c  = kc + 2;
            int ns = c - (c / NSTAGE) * NSTAGE;
            if (c >= NSTAGE)
                mbar_wait(mbe + ns * 8, (uint32_t)(((c - NSTAGE) / NSTAGE) & 1));
            mbar_expect_tx(mbf + ns * 8, STAGE_TX);
            tma2d(su + SM_A + ns * A_STAGE_BYTES, &tmA, c * KCHUNK, row0, mbf + ns * 8);
            tma2d(su + SM_B + ns * B_STAGE_BYTES, &tmB, c * KCHUNK, 0, mbf + ns * 8);
        }

        mbar_wait(mbf + s * 8, (uint32_t)phase);        // chunk kc resident

        const uint32_t abase = su + SM_A + s * A_STAGE_BYTES + a_tile_off;
        const uint32_t bbase = su + SM_B + s * B_STAGE_BYTES + b_tile_off;

        // fragment double-buffers
        uint32_t bu[2][4][2];
        uint32_t au[2][4];

        // initial loads: B(ks=0), A(ks=0, m=0)
        ldsm_x4(bu[0][0][0], bu[0][0][1], bu[0][1][0], bu[0][1][1], bbase + colB[0]);
        ldsm_x4(bu[0][2][0], bu[0][2][1], bu[0][3][0], bu[0][3][1], bbase + 2048u + colB[0]);
        ldsm_x4(au[0][0], au[0][1], au[0][2], au[0][3], abase + colA[0]);

#pragma unroll
        for (int ks = 0; ks < 4; ++ks) {
            const int bc = ks & 1, bn = bc ^ 1;
            if (ks < 3) {   // prefetch B for ks+1
                ldsm_x4(bu[bn][0][0], bu[bn][0][1], bu[bn][1][0], bu[bn][1][1],
                        bbase + colB[ks + 1]);
                ldsm_x4(bu[bn][2][0], bu[bn][2][1], bu[bn][3][0], bu[bn][3][1],
                        bbase + 2048u + colB[ks + 1]);
            }
#pragma unroll
            for (int m = 0; m < 4; ++m) {
                const int ac = m & 1, an = ac ^ 1;
                if (m < 3) {            // prefetch A for (ks, m+1)
                    ldsm_x4(au[an][0], au[an][1], au[an][2], au[an][3],
                            abase + (uint32_t)((m + 1) * 2048) + colA[ks]);
                } else if (ks < 3) {    // prefetch A for (ks+1, 0)
                    ldsm_x4(au[an][0], au[an][1], au[an][2], au[an][3],
                            abase + colA[ks + 1]);
                }
#pragma unroll
                for (int j = 0; j < 4; ++j) mma_tf32(acc[m][j], au[ac], bu[bc][j]);
            }
        }
        if (lane == 0) mbar_arrive(mbe + s * 8);        // this warp done with stage s
    }

    // ---- epilogue: e_r = sum_h va[h] * tanh(q[h] + C[r,h]) ; per-wc partials ----
#pragma unroll
    for (int m = 0; m < 4; ++m) {
#pragma unroll
        for (int rr = 0; rr < 2; ++rr) {
            float pa = 0.f;
#pragma unroll
            for (int j = 0; j < 4; ++j) {
#pragma unroll
                for (int cc = 0; cc < 2; ++cc) {
                    int h = wc * 32 + j * 8 + t * 2 + cc;
                    pa += vas[h] * tanh_fast(qs[h] + acc[m][j][rr * 2 + cc]);
                }
            }
            pa += __shfl_xor_sync(0xffffffffu, pa, 1);
            pa += __shfl_xor_sync(0xffffffffu, pa, 2);
            if (t == 0) es4[wc * 128 + wr * 64 + m * 16 + rr * 8 + g] = pa;
        }
    }
    __syncthreads();

    // energies bounded (|e| <= sum|va| ~= 11): exp without max-pass is safe
    if (tid < ROWS_PER_CTA) {
        float e = es4[tid] + es4[128 + tid] + es4[256 + tid] + es4[384 + tid];
        float p = __expf(e);
        ps[tid] = p;
        g_p[row0 + tid] = p;
        float s = p;
#pragma unroll
        for (int o = 16; o > 0; o >>= 1) s += __shfl_xor_sync(0xffffffffu, s, o);
        if (lane == 0) red[warp] = s;
    }
    __syncthreads();
    if (tid == 0) {
        float Z = 0.f;
#pragma unroll
        for (int i = 0; i < 4; ++i) Z += red[i];
        g_pz[bx] = Z;
    }
    __syncthreads();   // ps[] visible

    // ---- partial context: 2 row-halves of 64, two independent accumulators ----
    {
        const int c4 = (tid & 127) * 4;
        const int half = tid >> 7;               // 0 or 1
        const float* Xp = X + (size_t)(row0 + half * 64) * QK + c4;
        float4 a0 = make_float4(0.f, 0.f, 0.f, 0.f);
        float4 a1 = make_float4(0.f, 0.f, 0.f, 0.f);
#pragma unroll 8
        for (int l = 0; l < 64; l += 2) {
            float pl0 = ps[half * 64 + l];
            float pl1 = ps[half * 64 + l + 1];
            float4 x0 = *reinterpret_cast<const float4*>(Xp + (size_t)l * QK);
            float4 x1 = *reinterpret_cast<const float4*>(Xp + (size_t)(l + 1) * QK);
            a0.x += pl0 * x0.x; a0.y += pl0 * x0.y; a0.z += pl0 * x0.z; a0.w += pl0 * x0.w;
            a1.x += pl1 * x1.x; a1.y += pl1 * x1.y; a1.z += pl1 * x1.z; a1.w += pl1 * x1.w;
        }
        a0.x += a1.x; a0.y += a1.y; a0.z += a1.z; a0.w += a1.w;
        if (half == 1) *reinterpret_cast<float4*>(cst + c4) = a0;
        __syncthreads();
        if (half == 0) {
            float4 b = *reinterpret_cast<const float4*>(cst + c4);
            a0.x += b.x; a0.y += b.y; a0.z += b.z; a0.w += b.w;
            *reinterpret_cast<float4*>(&g_pc[(size_t)bx * QK + c4]) = a0;
        }
    }

    // ---- fan-in: last CTA of the batch combines ----
    __syncthreads();
    if (tid == 0) {
        __threadfence();
        int old = atomicAdd(&g_cnt[n], 1);
        s_last = (old == SPLITS - 1) ? 1 : 0;
    }
    __syncthreads();
    if (s_last) {
        __threadfence();
        float Z = 0.f;
#pragma unroll
        for (int i = 0; i < SPLITS; ++i) Z += g_pz[n * SPLITS + i];
        const float rZ = 1.f / Z;

        float* ctx = out;                       // (NB, QK)
        float* wts = out + (size_t)NB * QK;     // (NB, LL)
#pragma unroll
        for (int dd = 0; dd < QK / THREADS; ++dd) {
            int d = tid + dd * THREADS;
            float c = 0.f;
#pragma unroll
            for (int i = 0; i < SPLITS; ++i)
                c += g_pc[(size_t)(n * SPLITS + i) * QK + d];
            ctx[(size_t)n * QK + d] = c * rZ;
        }
#pragma unroll
        for (int i = 0; i < LL / THREADS; ++i) {
            int l = tid + i * THREADS;
            wts[(size_t)n * LL + l] = g_p[(size_t)n * LL + l] * rZ;
        }
        if (tid == 0) g_cnt[n] = 0;   // self-reset for next replay
    }
}

// ---------------- host: tensormap encode via runtime entry point (no -lcuda) ----------------
typedef CUresult (*tmap_encode_t)(
    CUtensorMap*, CUtensorMapDataType, cuuint32_t, void*,
    const cuuint64_t*, const cuuint64_t*, const cuuint32_t*, const cuuint32_t*,
    CUtensorMapInterleave, CUtensorMapSwizzle, CUtensorMapL2promotion, CUtensorMapFloatOOBfill);

extern "C" void kernel_launch(void* const* d_in, const int* in_sizes, int n_in,
                              void* d_out, int out_size) {
    const float* last_hidden     = (const float*)d_in[0];
    const float* encoder_outputs = (const float*)d_in[1];
    const float* Wa              = (const float*)d_in[2];
    const float* Ua              = (const float*)d_in[3];
    const float* va              = (const float*)d_in[4];
    float* out = (float*)d_out;

    static tmap_encode_t encode = nullptr;
    static bool attr_set = false;
    if (!attr_set) {
        cudaFuncSetAttribute(k_fused, cudaFuncAttributeMaxDynamicSharedMemorySize, SM_TOTAL);
        cudaDriverEntryPointQueryResult qr;
        void* fp = nullptr;
        cudaGetDriverEntryPoint("cuTensorMapEncodeTiled", &fp, cudaEnableDefault, &qr);
        encode = (tmap_encode_t)fp;
        attr_set = true;
    }

    CUtensorMap tmA, tmB;
    {
        cuuint64_t dims[2]   = {QK, (cuuint64_t)NB * LL};
        cuuint64_t stride[1] = {QK * sizeof(float)};
        cuuint32_t box[2]    = {KCHUNK, ROWS_PER_CTA};
        cuuint32_t elems[2]  = {1, 1};
        encode(&tmA, CU_TENSOR_MAP_DATA_TYPE_FLOAT32, 2, (void*)encoder_outputs,
               dims, stride, box, elems,
               CU_TENSOR_MAP_INTERLEAVE_NONE, CU_TENSOR_MAP_SWIZZLE_128B,
               CU_TENSOR_MAP_L2_PROMOTION_L2_128B, CU_TENSOR_MAP_FLOAT_OOB_FILL_NONE);
    }
    {
        cuuint64_t dims[2]   = {QK, HH};
        cuuint64_t stride[1] = {QK * sizeof(float)};
        cuuint32_t box[2]    = {KCHUNK, HH};
        cuuint32_t elems[2]  = {1, 1};
        encode(&tmB, CU_TENSOR_MAP_DATA_TYPE_FLOAT32, 2, (void*)Ua,
               dims, stride, box, elems,
               CU_TENSOR_MAP_INTERLEAVE_NONE, CU_TENSOR_MAP_SWIZZLE_128B,
               CU_TENSOR_MAP_L2_PROMOTION_L2_128B, CU_TENSOR_MAP_FLOAT_OOB_FILL_NONE);
    }

    k_qproj<<<NB, 512>>>(last_hidden, Wa);
    k_fused<<<NCTAS, THREADS, SM_TOTAL>>>(tmA, tmB, encoder_outputs, va, out);
}